// round 17
// baseline (speedup 1.0000x reference)
#include <cuda_runtime.h>
#include <cuda_bf16.h>

// Problem constants: P=Q=3, M=N=127, DIM=3, SU=SV=256, B=16
#define PB    16
#define PDEG  3
#define PM    127
#define PL    132          // knot vector length
#define PS    256          // samples per direction
#define PNC   128          // control points per direction
#define PDIM  3
#define PEPS  1e-8f
#define RG    4            // rows per block in rowsum kernel
#define TUC   4            // u's per block in ucontract kernel
#define GROWS 8            // zero-padded row window in ucontract kernel

// ---- device scratch (allocation-free) ----
__device__ float4 g_R[PB][PNC][PS];     // 8 MB rowsum scratch (L2-resident)
__device__ float4 g_nu4[PB][PS];        // u basis weights
__device__ int    g_iu[PB][PS];         // u window start (span - 3)

// ---------------------------------------------------------------------------
// One warp normalizes one knot vector entirely in registers, writes sK.
// cumsum order matches jnp.cumsum (sequential in index order).
// ---------------------------------------------------------------------------
__device__ __forceinline__ void warp_scan_knots(const float* __restrict__ knots,
                                                float* __restrict__ sK)
{
    const int lane = threadIdx.x & 31;
    const int CH = 5;                           // 32*5 >= 132
    const int base = lane * CH;
    float vch[CH];
    float run = 0.0f;
    #pragma unroll
    for (int k = 0; k < CH; k++) {
        int i = base + k;
        float x = 0.0f;
        if (i < PL) {
            x = knots[i];
            if (x < 0.0f) x = 0.0001f;
        }
        run += x;
        vch[k] = run;
    }
    float incl = run;
    #pragma unroll
    for (int off = 1; off < 32; off <<= 1) {
        float nb = __shfl_up_sync(0xffffffffu, incl, off);
        if (lane >= off) incl += nb;
    }
    const float excl = incl - run;
    const float sc0  = excl + vch[0];
    const float k0   = __shfl_sync(0xffffffffu, sc0, 0);
    const float last = __shfl_sync(0xffffffffu, incl, 31);
    const float inv  = 1.0f / (last - k0);
    #pragma unroll
    for (int k = 0; k < CH; k++) {
        int i = base + k;
        if (i < PL) sK[i] = ((excl + vch[k]) - k0) * inv;
    }
}

// span find (binary search + tie-walk, argmin semantics) + Cox-de Boor deg 3
__device__ __forceinline__ int basis_at(const float* sK, float t, float* Ni)
{
    int j;
    {
        const int cnt = PL - 2 * PDEG;          // 126
        int lo = 0, hi = cnt;
        while (lo < hi) {
            int mid = (lo + hi) >> 1;
            if (t - sK[PDEG + mid] > PEPS) lo = mid + 1;
            else hi = mid;
        }
        j = lo - 1;
        if (j < 0) j = 0;
        else {
            while (j > 0 && sK[PDEG + j - 1] == sK[PDEG + j]) j--;
        }
    }
    int span = j + PDEG;
    if (span < PDEG) span = PDEG;
    if (span > PM)   span = PM;

    Ni[0] = 1.0f; Ni[1] = 0.0f; Ni[2] = 0.0f; Ni[3] = 0.0f;
    #pragma unroll
    for (int k = 1; k <= PDEG; k++) {
        float saved = 0.0f;
        #pragma unroll
        for (int r = 0; r < PDEG; r++) {
            if (r >= k) break;
            float K1 = sK[span + r + 1];
            float K2 = sK[span + 1 - k + r];
            float denom = (K1 - t) + (t - K2);
            float temp = (denom == 0.0f) ? 0.0001f : __fdividef(Ni[r], denom);
            Ni[r] = saved + (K1 - t) * temp;
            saved = (t - K2) * temp;
        }
        Ni[k] = saved;
    }
    return span;
}

// ---------------------------------------------------------------------------
// Kernel 1: fused v-basis + rowsums; rchunk==0 blocks also build u tables.
// R[b][r][vv] = sum_q Nv[q][vv] * ctrl[b][r][iv+q][:]
// grid = B * (PNC/RG) = 512 blocks, blockDim = 256 (thread = vv).
// ---------------------------------------------------------------------------
__global__ void __launch_bounds__(PS)
surf_rowsum_kernel(const float* __restrict__ ctrl,
                   const float* __restrict__ knot_u,
                   const float* __restrict__ knot_v,
                   const float* __restrict__ u,
                   const float* __restrict__ v)
{
    const int b      = blockIdx.x / (PNC / RG);
    const int rchunk = blockIdx.x % (PNC / RG);
    const int rbase  = rchunk * RG;
    const int vv     = threadIdx.x;
    const int wid    = threadIdx.x >> 5;

    __shared__ float sK[PL];
    __shared__ float sKu[PL];

    if (wid == 0) warp_scan_knots(knot_v + b * PL, sK);
    else if (wid == 1 && rchunk == 0) warp_scan_knots(knot_u + b * PL, sKu);
    __syncthreads();

    float nv[PDEG + 1];
    const int iv = basis_at(sK, v[vv], nv) - PDEG;

    // u tables: 16 blocks, all 256 threads in parallel (one u-sample each)
    if (rchunk == 0) {
        float nu[PDEG + 1];
        const int us = basis_at(sKu, u[threadIdx.x], nu);
        g_iu[b][threadIdx.x]  = us - PDEG;
        g_nu4[b][threadIdx.x] = make_float4(nu[0], nu[1], nu[2], nu[3]);
    }

    const float* base = ctrl + (((long)b * PNC) * PNC + iv) * PDIM;

    #pragma unroll
    for (int j = 0; j < RG; j++) {
        const float* row = base + (long)(rbase + j) * (PNC * PDIM);
        float s0 = 0.0f, s1 = 0.0f, s2 = 0.0f;
        #pragma unroll
        for (int q = 0; q <= PDEG; q++) {
            const float w = nv[q];
            s0 = fmaf(w, __ldg(row + q * PDIM + 0), s0);
            s1 = fmaf(w, __ldg(row + q * PDIM + 1), s1);
            s2 = fmaf(w, __ldg(row + q * PDIM + 2), s2);
        }
        g_R[b][rbase + j][vv] = make_float4(s0, s1, s2, 0.0f);
    }
}

// ---------------------------------------------------------------------------
// Kernel 2: lean u-contraction from global R (no basis computation).
// out[b][uu][vv] = sum_p nu[uu][p] * R[b][iu[uu]+p][vv]
// grid = B * (PS/TUC) = 1024 blocks, blockDim = 256 (thread = vv).
// Per thread: ~8 coalesced LDG.128 + 96 FMA + 12 STG; prologue ~30 instrs.
// ---------------------------------------------------------------------------
__global__ void __launch_bounds__(PS)
surf_ucontract_kernel(float* __restrict__ out)
{
    const int b   = blockIdx.x / (PS / TUC);
    const int u0  = (blockIdx.x % (PS / TUC)) * TUC;
    const int vv  = threadIdx.x;
    const int tid = threadIdx.x;

    __shared__ int    s_iu[TUC];
    __shared__ float4 s_nu[TUC];
    __shared__ __align__(16) float s_w[GROWS][TUC];

    if (tid < TUC) {
        s_iu[tid] = g_iu[b][u0 + tid];
        s_nu[tid] = g_nu4[b][u0 + tid];
    }
    __syncthreads();

    float acc[TUC][PDIM];
    #pragma unroll
    for (int i = 0; i < TUC; i++) {
        acc[i][0] = 0.0f; acc[i][1] = 0.0f; acc[i][2] = 0.0f;
    }

    // grouped-window loop; typical case = one group of <= GROWS rows
    int done = 0;
    bool first = true;
    while (done < TUC) {
        const int rlo = s_iu[done];
        int gend = done;
        while (gend + 1 < TUC && s_iu[gend + 1] + PDEG - rlo < GROWS) gend++;

        if (!first) __syncthreads();            // prior reads of s_w complete

        // zero-padded weight table: w=0 for rows not in u i's window
        if (tid < GROWS * TUC) {
            const int j = tid / TUC, i = tid % TUC;
            float w = 0.0f;
            if (i >= done && i <= gend) {
                const int p = (rlo + j) - s_iu[i];
                if (p >= 0 && p <= PDEG) {
                    const float4 nu = s_nu[i];
                    w = (p == 0) ? nu.x : (p == 1) ? nu.y : (p == 2) ? nu.z : nu.w;
                }
            }
            s_w[j][i] = w;
        }
        __syncthreads();

        // 8 fixed rows (clamped; clamped rows provably weight-0)
        #pragma unroll
        for (int j = 0; j < GROWS; j++) {
            const int row = min(rlo + j, PNC - 1);
            const float4 r = __ldg(&g_R[b][row][vv]);       // coalesced LDG.128
            const float4 wa = *((const float4*)s_w[j]);     // broadcast LDS.128

            acc[0][0] = fmaf(wa.x, r.x, acc[0][0]); acc[0][1] = fmaf(wa.x, r.y, acc[0][1]); acc[0][2] = fmaf(wa.x, r.z, acc[0][2]);
            acc[1][0] = fmaf(wa.y, r.x, acc[1][0]); acc[1][1] = fmaf(wa.y, r.y, acc[1][1]); acc[1][2] = fmaf(wa.y, r.z, acc[1][2]);
            acc[2][0] = fmaf(wa.z, r.x, acc[2][0]); acc[2][1] = fmaf(wa.z, r.y, acc[2][1]); acc[2][2] = fmaf(wa.z, r.z, acc[2][2]);
            acc[3][0] = fmaf(wa.w, r.x, acc[3][0]); acc[3][1] = fmaf(wa.w, r.y, acc[3][1]); acc[3][2] = fmaf(wa.w, r.z, acc[3][2]);
        }

        first = false;
        done = gend + 1;
    }

    #pragma unroll
    for (int i = 0; i < TUC; i++) {
        float* o = out + (((long)b * PS + (u0 + i)) * PS + vv) * PDIM;
        o[0] = acc[i][0];
        o[1] = acc[i][1];
        o[2] = acc[i][2];
    }
}

// ---------------------------------------------------------------------------
extern "C" void kernel_launch(void* const* d_in, const int* in_sizes, int n_in,
                              void* d_out, int out_size)
{
    const float* ctrl   = (const float*)d_in[0];  // (B, 128, 128, 3)
    const float* knot_u = (const float*)d_in[1];  // (B, 132)
    const float* knot_v = (const float*)d_in[2];  // (B, 132)
    const float* u      = (const float*)d_in[3];  // (256,)
    const float* v      = (const float*)d_in[4];  // (256,)
    float* out = (float*)d_out;                   // (B, 256, 256, 3)

    surf_rowsum_kernel<<<PB * (PNC / RG), PS>>>(ctrl, knot_u, knot_v, u, v);
    surf_ucontract_kernel<<<PB * (PS / TUC), PS>>>(out);
}